// round 14
// baseline (speedup 1.0000x reference)
#include <cuda_runtime.h>
#include <cuda_bf16.h>
#include <math.h>
#include <stdint.h>

#define B_  2
#define T_  2048
typedef __nv_bfloat16 bf16;

// ---------------- scratch ----------------
__device__ bf16 g_xh[(size_t)4096 * 2048];             // x hi/lo
__device__ bf16 g_xl[(size_t)4096 * 2048];
__device__ bf16 g_wh[(size_t)4096 * 2048];             // [Wq | Wk | Wv] rows
__device__ bf16 g_wl[(size_t)4096 * 2048];
__device__ bf16 g_Qh[(size_t)B_ * 2 * 8 * T_ * 128];   // [b][y][h][t][d] hi (log2e-scaled)
__device__ bf16 g_Ql[(size_t)B_ * 2 * 8 * T_ * 128];
__device__ bf16 g_Kh[(size_t)B_ * 2 * 4 * T_ * 128];   // [b][y][kh][t][d]
__device__ bf16 g_Kl[(size_t)B_ * 2 * 4 * T_ * 128];
__device__ bf16 g_Vh[(size_t)B_ * T_ * 1024];          // [b*t][vh*256+vd]
__device__ bf16 g_Vl[(size_t)B_ * T_ * 1024];
__device__ float g_cos[T_ * 64];
__device__ float g_sin[T_ * 64];
__device__ float g_lam;

// ---------------- helpers ----------------
__device__ __forceinline__ uint32_t smem_u32(const void* p) {
    uint32_t a;
    asm("{ .reg .u64 t; cvta.to.shared.u64 t, %1; cvt.u32.u64 %0, t; }" : "=r"(a) : "l"(p));
    return a;
}
__device__ __forceinline__ void ldm4(uint32_t* r, uint32_t a) {
    asm volatile("ldmatrix.sync.aligned.m8n8.x4.shared.b16 {%0,%1,%2,%3}, [%4];"
                 : "=r"(r[0]), "=r"(r[1]), "=r"(r[2]), "=r"(r[3]) : "r"(a));
}
__device__ __forceinline__ void ldm4t(uint32_t* r, uint32_t a) {
    asm volatile("ldmatrix.sync.aligned.m8n8.x4.trans.shared.b16 {%0,%1,%2,%3}, [%4];"
                 : "=r"(r[0]), "=r"(r[1]), "=r"(r[2]), "=r"(r[3]) : "r"(a));
}
__device__ __forceinline__ float ex2f(float x) {
    float y;
    asm("ex2.approx.ftz.f32 %0, %1;" : "=f"(y) : "f"(x));
    return y;
}
#define MMA(d, a, b)                                                          \
    asm volatile("mma.sync.aligned.m16n8k16.row.col.f32.bf16.bf16.f32 "       \
                 "{%0,%1,%2,%3}, {%4,%5,%6,%7}, {%8,%9}, {%0,%1,%2,%3};"      \
                 : "+f"(d[0]), "+f"(d[1]), "+f"(d[2]), "+f"(d[3])             \
                 : "r"(a[0]), "r"(a[1]), "r"(a[2]), "r"(a[3]),                \
                   "r"(b[0]), "r"(b[1]))
#define CP16(dst, src)                                                        \
    asm volatile("cp.async.cg.shared.global [%0], [%1], 16;" :: "r"(dst), "l"(src))
#define CP_COMMIT() asm volatile("cp.async.commit_group;" ::: "memory")
#define CP_WAIT(n)  asm volatile("cp.async.wait_group %0;" :: "n"(n) : "memory")
#define BAR_PAIR(id) asm volatile("bar.sync %0, 64;" :: "r"(id) : "memory")

__device__ __forceinline__ uint32_t tchunk(int r, int c) {
    return (uint32_t)(((r >> 1) << 7) + ((((((r & 1) << 2) | c)) ^ ((r >> 1) & 7)) << 4));
}
__device__ __forceinline__ uint32_t pk2(float x, float y) {
    __nv_bfloat162 h;
    h.x = __float2bfloat16(x);
    h.y = __float2bfloat16(y);
    return *reinterpret_cast<uint32_t*>(&h);
}
__device__ __forceinline__ void packhl(float x, float y, uint32_t& hi, uint32_t& lo) {
    bf16 hx = __float2bfloat16(x), hy = __float2bfloat16(y);
    __nv_bfloat162 h; h.x = hx; h.y = hy;
    hi = *reinterpret_cast<uint32_t*>(&h);
    lo = pk2(x - __bfloat162float(hx), y - __bfloat162float(hy));
}

// ---------------- prep: hi/lo split + RoPE table + lambda (one launch) ----------------
__global__ __launch_bounds__(256) void prep_kernel(const float* __restrict__ x,
                                                   const float* __restrict__ wq,
                                                   const float* __restrict__ wk,
                                                   const float* __restrict__ wv,
                                                   const float* __restrict__ lq1,
                                                   const float* __restrict__ lk1,
                                                   const float* __restrict__ lq2,
                                                   const float* __restrict__ lk2) {
    int y = blockIdx.y;
    if (y == 4) {
        if (blockIdx.x >= 64 || threadIdx.x >= 64) return;
        int i = threadIdx.x;
        double invf = 1.0 / pow(10000.0, (double)(2 * i) / 128.0);
        float invff = (float)invf;
        int t0 = blockIdx.x * 32;
        for (int j = 0; j < 32; j++) {
            int t = t0 + j;
            float angle = (float)t * invff;
            float s, c;
            sincosf(angle, &s, &c);
            g_cos[t * 64 + i] = __bfloat162float(__float2bfloat16(c));
            g_sin[t * 64 + i] = __bfloat162float(__float2bfloat16(s));
        }
        if (blockIdx.x == 0 && i == 0) {
            float s1 = 0.f, s2 = 0.f;
            for (int j = 0; j < 64; j++) { s1 += lq1[j] * lk1[j]; s2 += lq2[j] * lk2[j]; }
            g_lam = expf(s1) - expf(s2) + 0.2f;
        }
        return;
    }
    const float* src;
    bf16 *dh, *dl;
    int n4;
    if (y == 0)      { src = x;  dh = g_xh;           dl = g_xl;           n4 = 2097152; }
    else if (y == 1) { src = wq; dh = g_wh;           dl = g_wl;           n4 = 1048576; }
    else if (y == 2) { src = wk; dh = g_wh + 4194304; dl = g_wl + 4194304; n4 = 524288;  }
    else             { src = wv; dh = g_wh + 6291456; dl = g_wl + 6291456; n4 = 524288;  }
    int idx = blockIdx.x * 256 + threadIdx.x;
    if (idx < n4) {
        float4 v = ((const float4*)src)[idx];
        uint32_t h0, l0, h1, l1;
        packhl(v.x, v.y, h0, l0);
        packhl(v.z, v.w, h1, l1);
        *(uint2*)(dh + (size_t)idx * 4) = make_uint2(h0, h1);
        *(uint2*)(dl + (size_t)idx * 4) = make_uint2(l0, l1);
    }
}

// ---------------- bf16x3 HMMA QKV GEMM: 64x128 tiles, 3-stage, 3 CTA/SM ----------------
// stage (24KB at slot*24576): Ah 4K | Al 4K | Bh 8K | Bl 8K   (rows x 32 bf16, swizzled)
#define GSTG 24576
#define GEMM_SMEM (3 * GSTG)

__global__ __launch_bounds__(256, 3)
void qkv_gemm_tc(const float* __restrict__ scaler) {
    extern __shared__ char sm[];
    uint32_t sb = smem_u32(sm);
    int tid = threadIdx.x;
    int wid = tid >> 5, lane = tid & 31;
    int wy = wid >> 2, wx = wid & 3;

    int bid = blockIdx.x;
    int type, bx, by;
    if (bid < 1024)      { type = 0; bx = bid & 15; by = bid >> 4; }
    else if (bid < 1536) { int u = bid - 1024; type = 1; bx = u & 7; by = u >> 3; }
    else                 { int u = bid - 1536; type = 2; bx = u & 7; by = u >> 3; }
    int row0 = by * 64, col0 = bx * 128;
    int wrow0 = col0 + (type == 0 ? 0 : (type == 1 ? 2048 : 3072));
    const bf16* pa[2] = { g_xh + (size_t)row0 * 2048, g_xl + (size_t)row0 * 2048 };
    const bf16* pw[2] = { g_wh + (size_t)wrow0 * 2048, g_wl + (size_t)wrow0 * 2048 };

    auto g_issue = [&](int kc, int slot) {
        uint32_t st = sb + slot * GSTG;
#pragma unroll
        for (int it = 0; it < 6; it++) {
            int i = tid + it * 256;                  // 0..1535
            if (i < 512) {
                int plane = i >> 8, r = (i >> 2) & 63, ch = i & 3;
                const bf16* src = pa[plane] + (size_t)r * 2048 + kc * 32 + ch * 8;
                CP16(st + plane * 4096 + tchunk(r, ch), src);
            } else {
                int j = i - 512;
                int plane = j >> 9, r = (j >> 2) & 127, ch = j & 3;
                const bf16* src = pw[plane] + (size_t)r * 2048 + kc * 32 + ch * 8;
                CP16(st + 8192 + plane * 8192 + tchunk(r, ch), src);
            }
        }
        CP_COMMIT();
    };

    int a_row = (lane & 7) + ((lane >> 3) & 1) * 8;
    int a_ch  = lane >> 4;
    int b_row = (lane & 7) + (lane >> 4) * 8;
    int b_ch  = (lane >> 3) & 1;
    uint32_t aoff[2][2], boff[2][2];
#pragma unroll
    for (int mt = 0; mt < 2; mt++)
#pragma unroll
        for (int ks = 0; ks < 2; ks++)
            aoff[mt][ks] = tchunk(wy * 32 + mt * 16 + a_row, 2 * ks + a_ch);
#pragma unroll
    for (int nb = 0; nb < 2; nb++)
#pragma unroll
        for (int ks = 0; ks < 2; ks++)
            boff[nb][ks] = tchunk(wx * 32 + nb * 16 + b_row, 2 * ks + b_ch);

    float acc[2][4][4];
#pragma unroll
    for (int i = 0; i < 2; i++)
#pragma unroll
        for (int j = 0; j < 4; j++)
#pragma unroll
            for (int k = 0; k < 4; k++) acc[i][j][k] = 0.f;

    g_issue(0, 0); g_issue(1, 1);
    for (int kc = 0; kc < 64; kc++) {
        if (kc + 1 < 64) { CP_WAIT(1); }
        else             { CP_WAIT(0); }
        __syncthreads();
        if (kc + 2 < 64) g_issue(kc + 2, (kc + 2) % 3);
        uint32_t stb = sb + (kc % 3) * GSTG;
#pragma unroll
        for (int ks = 0; ks < 2; ks++) {
            uint32_t Ahf[2][4], Alf[2][4];
#pragma unroll
            for (int mt = 0; mt < 2; mt++) {
                ldm4(Ahf[mt], stb + aoff[mt][ks]);
                ldm4(Alf[mt], stb + 4096 + aoff[mt][ks]);
            }
#pragma unroll
            for (int nb = 0; nb < 2; nb++) {
                uint32_t rh[4], rl[4];
                ldm4(rh, stb + 8192 + boff[nb][ks]);
                ldm4(rl, stb + 16384 + boff[nb][ks]);
                uint32_t bh0[2] = {rh[0], rh[1]}, bh1[2] = {rh[2], rh[3]};
                uint32_t bl0[2] = {rl[0], rl[1]}, bl1[2] = {rl[2], rl[3]};
#pragma unroll
                for (int mt = 0; mt < 2; mt++) {
                    MMA(acc[mt][2*nb],   Ahf[mt], bh0);
                    MMA(acc[mt][2*nb],   Ahf[mt], bl0);
                    MMA(acc[mt][2*nb],   Alf[mt], bh0);
                    MMA(acc[mt][2*nb+1], Ahf[mt], bh1);
                    MMA(acc[mt][2*nb+1], Ahf[mt], bl1);
                    MMA(acc[mt][2*nb+1], Alf[mt], bh1);
                }
            }
        }
    }
    __syncthreads();

    float* buf1 = (float*)sm;   // [64][132] = 33.8KB < 72KB
#pragma unroll
    for (int mt = 0; mt < 2; mt++)
#pragma unroll
        for (int n = 0; n < 4; n++) {
            int r = wy * 32 + mt * 16 + (lane >> 2);
            int c = wx * 32 + n * 8 + (lane & 3) * 2;
            *(float2*)&buf1[r * 132 + c]       = make_float2(acc[mt][n][0], acc[mt][n][1]);
            *(float2*)&buf1[(r + 8) * 132 + c] = make_float2(acc[mt][n][2], acc[mt][n][3]);
        }
    __syncthreads();

    if (type == 2) {
        for (int i = tid; i < 2048; i += 256) {
            int r = i >> 5, c4 = i & 31;
            float4 v = *(const float4*)&buf1[r * 132 + c4 * 4];
            uint32_t h0, l0, h1, l1;
            packhl(v.x, v.y, h0, l0); packhl(v.z, v.w, h1, l1);
            size_t off = (size_t)(row0 + r) * 1024 + col0 + c4 * 4;
            *(uint2*)(g_Vh + off) = make_uint2(h0, h1);
            *(uint2*)(g_Vl + off) = make_uint2(l0, l1);
        }
        return;
    }

    // Q/K epilogue: 2 threads per row (tid<128), shuffle-combined rms
    if (tid < 128) {
        int row = tid >> 1, half = tid & 1;
        int b = row0 >> 11;
        int ttok = (row0 & (T_ - 1)) + row;
        const float* rowp = &buf1[row * 132];
        float ss = 0.f;
#pragma unroll
        for (int c4 = 0; c4 < 16; c4++) {
            float4 v = *(const float4*)&rowp[half * 64 + c4 * 4];
            ss = fmaf(v.x, v.x, fmaf(v.y, v.y, fmaf(v.z, v.z, fmaf(v.w, v.w, ss))));
        }
        ss += __shfl_xor_sync(0xffffffffu, ss, 1);
        float rn = rsqrtf(ss * (1.0f / 128.0f) + 1.1920929e-07f);
        float f = (type == 0) ? rn * scaler[bx] * logf((float)(ttok + 1)) *
                                0.08838834764831845f * 1.4426950408889634f
                              : rn;
        float ov0[32], ov1[32];   // cols half*32+j  and  64+half*32+j
#pragma unroll
        for (int j = 0; j < 32; j++) {
            int i = half * 32 + j;
            float c = g_cos[ttok * 64 + i], s = g_sin[ttok * 64 + i];
            float x1 = rowp[i], x2 = rowp[i + 64];
            ov0[j] = ( x1 * c + x2 * s) * f;
            ov1[j] = (-x1 * s + x2 * c) * f;
        }
        size_t rbase;
        bf16 *dh, *dl;
        if (type == 0) {
            rbase = ((size_t)((b * 2 + (bx >> 3)) * 8 + (bx & 7)) * T_ + ttok) * 128;
            dh = g_Qh + rbase; dl = g_Ql + rbase;
        } else {
            rbase = ((size_t)((b * 2 + (bx >> 2)) * 4 + (bx & 3)) * T_ + ttok) * 128;
            dh = g_Kh + rbase; dl = g_Kl + rbase;
        }
#pragma unroll
        for (int c4 = 0; c4 < 8; c4++) {
            uint32_t h0, l0, h1, l1;
            packhl(ov0[c4*4], ov0[c4*4+1], h0, l0);
            packhl(ov0[c4*4+2], ov0[c4*4+3], h1, l1);
            *(uint2*)(dh + half * 32 + c4 * 4) = make_uint2(h0, h1);
            *(uint2*)(dl + half * 32 + c4 * 4) = make_uint2(l0, l1);
            packhl(ov1[c4*4], ov1[c4*4+1], h0, l0);
            packhl(ov1[c4*4+2], ov1[c4*4+3], h1, l1);
            *(uint2*)(dh + 64 + half * 32 + c4 * 4) = make_uint2(h0, h1);
            *(uint2*)(dl + 64 + half * 32 + c4 * 4) = make_uint2(l0, l1);
        }
    }
}

// ---------------- HMMA diff causal flash attention (R13 + pair barrier for SMAX) ----------
#define STAT_MAX 196608
#define STAT_SUM 197120
#define P_BASE   197632
#define P_BUF    12288
#define ATT_SMEM (P_BASE + 2 * P_BUF)

__global__ __launch_bounds__(256, 1) void diff_attn_hmma(float* __restrict__ out) {
    extern __shared__ char sm[];
    uint32_t sb = smem_u32(sm);
    int tid = threadIdx.x, lane = tid & 31, wid = tid >> 5;
    int y = wid >> 2, qs = (wid >> 1) & 1, vh = wid & 1;
    int qt = 63 - blockIdx.x;
    int h = blockIdx.y, b = blockIdx.z;
    int q0 = qt * 32;
    int g = lane >> 2, t2 = (lane & 3) << 1;
    int kh = h >> 1;
    int widx  = (y * 2 + qs) * 2 + vh;
    int pwidx = widx ^ 1;
    int pair_bar = 1 + (widx >> 1);

    const bf16* Kp[2][2];
    Kp[0][0] = g_Kh + ((size_t)((b * 2 + 0) * 4 + kh) * T_) * 128;
    Kp[0][1] = g_Kl + ((size_t)((b * 2 + 0) * 4 + kh) * T_) * 128;
    Kp[1][0] = g_Kh + ((size_t)((b * 2 + 1) * 4 + kh) * T_) * 128;
    Kp[1][1] = g_Kl + ((size_t)((b * 2 + 1) * 4 + kh) * T_) * 128;
    const bf16* Vp[2];
    Vp[0] = g_Vh + (size_t)b * T_ * 1024 + kh * 256;
    Vp[1] = g_Vl + (size_t)b * T_ * 1024 + kh * 256;

    uint32_t Qh[8][4], Ql[8][4];
    {
        const bf16* Qp[2][2];
        Qp[0][0] = g_Qh + ((size_t)((b * 2 + 0) * 8 + h) * T_ + q0) * 128;
        Qp[0][1] = g_Ql + ((size_t)((b * 2 + 0) * 8 + h) * T_ + q0) * 128;
        Qp[1][0] = g_Qh + ((size_t)((b * 2 + 1) * 8 + h) * T_ + q0) * 128;
        Qp[1][1] = g_Ql + ((size_t)((b * 2 + 1) * 8 + h) * T_ + q0) * 128;
#pragma unroll
        for (int it = 0; it < 8; it++) {
            int i = tid + it * 256;
            int br = i >> 10, hl = (i >> 9) & 1, qq = (i >> 4) & 31, c = i & 15;
            uint4 v = *(const uint4*)(Qp[br][hl] + (size_t)qq * 128 + c * 8);
            *(uint4*)(sm + ((br * 2 + hl) * 4 + (c >> 2)) * 2048 + tchunk(qq, c & 3)) = v;
        }
        __syncthreads();
        int a_row = (lane & 7) + ((lane >> 3) & 1) * 8;
        int a_ch  = lane >> 4;
#pragma unroll
        for (int kc = 0; kc < 8; kc++) {
            uint32_t off = tchunk(qs * 16 + a_row, 2 * (kc & 1) + a_ch);
            ldm4(Qh[kc], sb + ((y * 2 + 0) * 4 + (kc >> 1)) * 2048 + off);
            ldm4(Ql[kc], sb + ((y * 2 + 1) * 4 + (kc >> 1)) * 2048 + off);
        }
        __syncthreads();
    }

    float m0 = -INFINITY, m1 = -INFINITY, l0 = 0.f, l1 = 0.f;
    float oacc[16][4];
#pragma unroll
    for (int n = 0; n < 16; n++)
#pragma unroll
        for (int j = 0; j < 4; j++) oacc[n][j] = 0.f;

    int b_row = (lane & 7) + (lane >> 4) * 8;
    int b_ch  = (lane >> 3) & 1;
    uint32_t kboff[2];
#pragma unroll
    for (int ks = 0; ks < 2; ks++)
        kboff[ks] = tchunk(vh * 16 + b_row, 2 * ks + b_ch);

    float* SMAX = (float*)(sm + STAT_MAX);
    float* SSUM = (float*)(sm + STAT_SUM);
    uint32_t pw_lane_off = (uint32_t)((lane & 15) * 48 + (lane >> 4) * 16);

    int nt = qt + 1;

    auto stage_issue = [&](int kt, int slot) {
        uint32_t kb = sb + slot * 65536;
        uint32_t vb = kb + 32768;
        int k0 = kt * 32;
#pragma unroll
        for (int it = 0; it < 8; it++) {
            int i = tid + it * 256;
            int br = i >> 10, hl = (i >> 9) & 1, kk = (i >> 4) & 31, c = i & 15;
            const bf16* src = Kp[br][hl] + (size_t)(k0 + kk) * 128 + c * 8;
            CP16(kb + ((br * 2 + hl) * 4 + (c >> 2)) * 2048 + tchunk(kk, c & 3), src);
        }
#pragma unroll
        for (int it = 0; it < 8; it++) {
            int i = tid + it * 256;
            int hl = i >> 10, kk = (i >> 5) & 31, c = i & 31;
            const bf16* src = Vp[hl] + (size_t)(k0 + kk) * 1024 + c * 8;
            CP16(vb + hl * 16384 + kk * 512 + ((c ^ (kk & 7)) << 4), src);
        }
        CP_COMMIT();
    };

    uint32_t pha[4], pla[4];

    auto pv_accum = [&](uint32_t vbp, int pbuf) {
        uint32_t PR = sb + P_BASE + (uint32_t)pbuf * P_BUF + (uint32_t)pwidx * 1536 +
                      pw_lane_off;
        uint32_t phP[4], plP[4];
        ldm4(phP, PR);
        ldm4(plP, PR + 768);
#pragma unroll
        for (int kk = 0; kk < 2; kk++) {
            const uint32_t* PH = (kk == vh) ? pha : phP;
            const uint32_t* PL = (kk == vh) ? pla : plP;
            int krow = kk * 16 + (lane & 15);
            uint32_t rowadr = (uint32_t)(krow * 512);
            int swz = krow & 7;
#pragma unroll
            for (int ng = 0; ng < 8; ng++) {
                int lch = vh * 16 + ng * 2 + (lane >> 4);
                uint32_t ah = vbp + rowadr + (uint32_t)((lch ^ swz) << 4);
                uint32_t r4[4];
                ldm4t(r4, ah);
                uint32_t bvh0[2] = {r4[0], r4[1]}, bvh1[2] = {r4[2], r4[3]};
                uint32_t s4[4];
                ldm4t(s4, ah + 16384);
                uint32_t bvl0[2] = {s4[0], s4[1]}, bvl1[2] = {s4[2], s4[3]};
                MMA(oacc[2*ng],   PH, bvh0);
                MMA(oacc[2*ng],   PH, bvl0);
                MMA(oacc[2*ng],   PL, bvh0);
                MMA(oacc[2*ng+1], PH, bvh1);
                MMA(oacc[2*ng+1], PH, bvl1);
                MMA(oacc[2*ng+1], PL, bvh1);
            }
        }
    };

    stage_issue(0, 0);
    if (nt > 1) stage_issue(1, 1);
    for (int kt = 0; kt < nt; kt++) {
        if (kt + 1 < nt) { CP_WAIT(1); }
        else             { CP_WAIT(0); }
        __syncthreads();
        uint32_t kb = sb + (kt % 3) * 65536;
        int k0 = kt * 32;

        float sh[2][4], sca[2][4], scb[2][4];
#pragma unroll
        for (int n = 0; n < 2; n++)
#pragma unroll
            for (int j = 0; j < 4; j++) { sh[n][j] = 0.f; sca[n][j] = 0.f; scb[n][j] = 0.f; }
#pragma unroll
        for (int kc = 0; kc < 8; kc++) {
            uint32_t ph_ = kb + ((y * 2 + 0) * 4 + (kc >> 1)) * 2048;
            uint32_t pl_ = kb + ((y * 2 + 1) * 4 + (kc >> 1)) * 2048;
            uint32_t off = kboff[kc & 1];
            uint32_t rh[4], rl[4];
            ldm4(rh, ph_ + off);
            ldm4(rl, pl_ + off);
            uint32_t bh0[2] = {rh[0], rh[1]}, bh1[2] = {rh[2], rh[3]};
            uint32_t bl0[2] = {rl[0], rl[1]}, bl1[2] = {rl[2], rl[3]};
            MMA(sh[0],  Qh[kc], bh0);
            MMA(sca[0], Qh[kc], bl0);
            MMA(scb[0], Ql[kc], bh0);
            MMA(sh[1],  Qh[kc], bh1);
            MMA(sca[1], Qh[kc], bl1);
            MMA(scb[1], Ql[kc], bh1);
        }
#pragma unroll
        for (int n = 0; n < 2; n++)
#pragma unroll
            for (int j = 0; j < 4; j++) sh[n][j] += sca[n][j] + scb[n][j];

        if (kt == qt) {
            int r0 = q0 + qs * 16 + g, r1 = r0 + 8;
#pragma unroll
            for (int n = 0; n < 2; n++) {
                int c = k0 + vh * 16 + n * 8 + t2;
                if (c     > r0) sh[n][0] = -INFINITY;
                if (c + 1 > r0) sh[n][1] = -INFINITY;
                if (c     > r1) sh[n][2] = -INFINITY;
                if (c + 1 > r1) sh[n][3] = -INFINITY;
            }
        }

        if (kt > 0) pv_accum(sb + ((kt + 2) % 3) * 65536 + 32768, (kt - 1) & 1);

        float mx0 = fmaxf(fmaxf(sh[0][0], sh[0][1]), fmaxf(sh[1][0], sh[1][1]));
        float mx1 = fmaxf(fmaxf(sh[0][2], sh[0][3]), fmaxf(sh[1][2], sh[1][3]));
        mx0 = fmaxf(mx0, __shfl_xor_sync(0xffffffffu, mx0, 1));
        mx0 = fmaxf(mx0, __shfl_xor_sync(0xffffffffu, mx0, 2));
        mx1 = fmaxf(mx1, __shfl_xor_sync(0xffffffffu, mx1, 1));
        mx1 = fmaxf(mx1, __shfl_xor_sync(0xffffffffu, mx1, 2));
        if ((lane & 3) == 0) {
            SMAX[widx * 16 + g]     = mx0;
            SMAX[widx * 16 + g + 8] = mx1;
        }
        BAR_PAIR(pair_bar);
        float mn0 = fmaxf(m0, fmaxf(mx0, SMAX[pwidx * 16 + g]));
        float mn1 = fmaxf(m1, fmaxf(mx1, SMAX[pwidx * 16 + g + 8]));
        float a0 = ex2f(m0 - mn0), a1 = ex2f(m1 - mn1);
        m0 = mn0; m1 = mn1;

        float s0 = 0.f, s1 = 0.f;
#pragma unroll
        for (int n = 0; n < 2; n++) {
            sh[n][0] = ex2f(sh[n][0] - mn0); s0 += sh[n][0];
            sh[n][1] = ex2f(sh[n][1] - mn0); s0 += sh[n][1];
            sh[n][2] = ex2f(sh[n][2] - mn1); s1 += sh[n][2];
            sh[n][3] = ex2f(sh[n][3] - mn1); s1 += sh[n][3];
        }
        s0 += __shfl_xor_sync(0xffffffffu, s0, 1);
        s0 += __shfl_xor_sync(0xffffffffu, s0, 2);
        s1 += __shfl_xor_sync(0xffffffffu, s1, 1);
        s1 += __shfl_xor_sync(0xffffffffu, s1, 2);

        packhl(sh[0][0], sh[0][1], pha[0], pla[0]);
        packhl(sh[0][2], sh[0][3], pha[1], pla[1]);
        packhl(sh[1][0], sh[1][1], pha[2], pla[2]);
        packhl(sh[1][2], sh[1][3], pha[3], pla[3]);
        {
            char* PW = sm + P_BASE + (kt & 1) * P_BUF + widx * 1536;
            *(uint32_t*)(PW + g * 48 + t2 * 2)              = pha[0];
            *(uint32_t*)(PW + (g + 8) * 48 + t2 * 2)        = pha[1];
            *(uint32_t*)(PW + g * 48 + 16 + t2 * 2)         = pha[2];
            *(uint32_t*)(PW + (g + 8) * 48 + 16 + t2 * 2)   = pha[3];
            *(uint32_t*)(PW + 768 + g * 48 + t2 * 2)            = pla[0];
            *(uint32_t*)(PW + 768 + (g + 8) * 48 + t2 * 2)      = pla[1];
            *(uint32_t*)(PW + 768 + g * 48 + 16 + t2 * 2)       = pla[2];
            *(uint32_t*)(PW + 768 + (g + 8) * 48 + 16 + t2 * 2) = pla[3];
        }
        if ((lane & 3) == 0) {
            SSUM[widx * 16 + g]     = s0;
            SSUM[widx * 16 + g + 8] = s1;
        }
        __syncthreads();
        l0 = l0 * a0 + s0 + SSUM[pwidx * 16 + g];
        l1 = l1 * a1 + s1 + SSUM[pwidx * 16 + g + 8];

        if (!__all_sync(0xffffffffu, (a0 == 1.f) && (a1 == 1.f))) {
#pragma unroll
            for (int n = 0; n < 16; n++) {
                oacc[n][0] *= a0; oacc[n][1] *= a0;
                oacc[n][2] *= a1; oacc[n][3] *= a1;
            }
        }

        if (kt + 2 < nt) stage_issue(kt + 2, (kt + 2) % 3);
    }
    pv_accum(sb + ((nt - 1) % 3) * 65536 + 32768, (nt - 1) & 1);

    __syncthreads();
    float i0 = 1.f / l0, i1 = 1.f / l1;
    float* Ob = (float*)sm + y * 8192;
#pragma unroll
    for (int n = 0; n < 16; n++) {
        int col = vh * 128 + n * 8 + t2;
        int r = qs * 16 + g;
        Ob[r * 256 + col]           = oacc[n][0] * i0;
        Ob[r * 256 + col + 1]       = oacc[n][1] * i0;
        Ob[(r + 8) * 256 + col]     = oacc[n][2] * i1;
        Ob[(r + 8) * 256 + col + 1] = oacc[n][3] * i1;
    }
    __syncthreads();
    float lam = g_lam;
    float* O0 = (float*)sm;
    float* O1 = (float*)sm + 8192;
    for (int i = tid; i < 2048; i += 256) {
        int r = i >> 6, c4 = i & 63;
        float4 v1 = *(const float4*)&O0[r * 256 + c4 * 4];
        float4 v2 = *(const float4*)&O1[r * 256 + c4 * 4];
        float4 o = {v1.x - lam * v2.x, v1.y - lam * v2.y,
                    v1.z - lam * v2.z, v1.w - lam * v2.w};
        *(float4*)&out[((size_t)(b * T_ + q0 + r) * 8 + h) * 256 + c4 * 4] = o;
    }
}

// ---------------- launch ----------------
extern "C" void kernel_launch(void* const* d_in, const int* in_sizes, int n_in,
                              void* d_out, int out_size) {
    const float* x      = (const float*)d_in[0];
    const float* Wq     = (const float*)d_in[1];
    const float* Wk     = (const float*)d_in[2];
    const float* Wv     = (const float*)d_in[3];
    const float* lq1    = (const float*)d_in[4];
    const float* lk1    = (const float*)d_in[5];
    const float* lq2    = (const float*)d_in[6];
    const float* lk2    = (const float*)d_in[7];
    const float* scaler = (const float*)d_in[8];
    float* out = (float*)d_out;

    prep_kernel<<<dim3(8192, 5), 256>>>(x, Wq, Wk, Wv, lq1, lk1, lq2, lk2);

    cudaFuncSetAttribute(qkv_gemm_tc, cudaFuncAttributeMaxDynamicSharedMemorySize, GEMM_SMEM);
    qkv_gemm_tc<<<2048, 256, GEMM_SMEM>>>(scaler);

    cudaFuncSetAttribute(diff_attn_hmma, cudaFuncAttributeMaxDynamicSharedMemorySize, ATT_SMEM);
    diff_attn_hmma<<<dim3(64, 8, B_), 256, ATT_SMEM>>>(out);
}

// round 15
// speedup vs baseline: 1.0288x; 1.0288x over previous
#include <cuda_runtime.h>
#include <cuda_bf16.h>
#include <math.h>
#include <stdint.h>

#define B_  2
#define T_  2048
typedef __nv_bfloat16 bf16;

// ---------------- scratch ----------------
__device__ bf16 g_xh[(size_t)4096 * 2048];             // x hi/lo
__device__ bf16 g_xl[(size_t)4096 * 2048];
__device__ bf16 g_wh[(size_t)4096 * 2048];             // [Wq | Wk | Wv] rows
__device__ bf16 g_wl[(size_t)4096 * 2048];
__device__ bf16 g_Qh[(size_t)B_ * 2 * 8 * T_ * 128];   // [b][y][h][t][d] hi (log2e-scaled)
__device__ bf16 g_Ql[(size_t)B_ * 2 * 8 * T_ * 128];
__device__ bf16 g_Kh[(size_t)B_ * 2 * 4 * T_ * 128];   // [b][y][kh][t][d]
__device__ bf16 g_Kl[(size_t)B_ * 2 * 4 * T_ * 128];
__device__ bf16 g_Vh[(size_t)B_ * T_ * 1024];          // [b*t][vh*256+vd]
__device__ bf16 g_Vl[(size_t)B_ * T_ * 1024];
__device__ float g_cos[T_ * 64];
__device__ float g_sin[T_ * 64];
__device__ float g_lam;

// ---------------- helpers ----------------
__device__ __forceinline__ uint32_t smem_u32(const void* p) {
    uint32_t a;
    asm("{ .reg .u64 t; cvta.to.shared.u64 t, %1; cvt.u32.u64 %0, t; }" : "=r"(a) : "l"(p));
    return a;
}
__device__ __forceinline__ void ldm4(uint32_t* r, uint32_t a) {
    asm volatile("ldmatrix.sync.aligned.m8n8.x4.shared.b16 {%0,%1,%2,%3}, [%4];"
                 : "=r"(r[0]), "=r"(r[1]), "=r"(r[2]), "=r"(r[3]) : "r"(a));
}
__device__ __forceinline__ void ldm4t(uint32_t* r, uint32_t a) {
    asm volatile("ldmatrix.sync.aligned.m8n8.x4.trans.shared.b16 {%0,%1,%2,%3}, [%4];"
                 : "=r"(r[0]), "=r"(r[1]), "=r"(r[2]), "=r"(r[3]) : "r"(a));
}
__device__ __forceinline__ float ex2f(float x) {
    float y;
    asm("ex2.approx.ftz.f32 %0, %1;" : "=f"(y) : "f"(x));
    return y;
}
#define MMA(d, a, b)                                                          \
    asm volatile("mma.sync.aligned.m16n8k16.row.col.f32.bf16.bf16.f32 "       \
                 "{%0,%1,%2,%3}, {%4,%5,%6,%7}, {%8,%9}, {%0,%1,%2,%3};"      \
                 : "+f"(d[0]), "+f"(d[1]), "+f"(d[2]), "+f"(d[3])             \
                 : "r"(a[0]), "r"(a[1]), "r"(a[2]), "r"(a[3]),                \
                   "r"(b[0]), "r"(b[1]))
#define CP16(dst, src)                                                        \
    asm volatile("cp.async.cg.shared.global [%0], [%1], 16;" :: "r"(dst), "l"(src))
#define CP_COMMIT() asm volatile("cp.async.commit_group;" ::: "memory")
#define CP_WAIT(n)  asm volatile("cp.async.wait_group %0;" :: "n"(n) : "memory")

__device__ __forceinline__ uint32_t tchunk(int r, int c) {
    return (uint32_t)(((r >> 1) << 7) + ((((((r & 1) << 2) | c)) ^ ((r >> 1) & 7)) << 4));
}
__device__ __forceinline__ uint32_t pk2(float x, float y) {
    __nv_bfloat162 h;
    h.x = __float2bfloat16(x);
    h.y = __float2bfloat16(y);
    return *reinterpret_cast<uint32_t*>(&h);
}
__device__ __forceinline__ void packhl(float x, float y, uint32_t& hi, uint32_t& lo) {
    bf16 hx = __float2bfloat16(x), hy = __float2bfloat16(y);
    __nv_bfloat162 h; h.x = hx; h.y = hy;
    hi = *reinterpret_cast<uint32_t*>(&h);
    lo = pk2(x - __bfloat162float(hx), y - __bfloat162float(hy));
}

// ---------------- prep: hi/lo split (flat, 2 f4/thread) + RoPE + lambda ----------------
// blocks 0..8191: split (512 f4 per block); blocks 8192..8255: rope table.
__global__ __launch_bounds__(256) void prep_kernel(const float* __restrict__ x,
                                                   const float* __restrict__ wq,
                                                   const float* __restrict__ wk,
                                                   const float* __restrict__ wv,
                                                   const float* __restrict__ lq1,
                                                   const float* __restrict__ lk1,
                                                   const float* __restrict__ lq2,
                                                   const float* __restrict__ lk2) {
    int blk = blockIdx.x;
    if (blk >= 8192) {
        if (threadIdx.x >= 64) return;
        int i = threadIdx.x;
        double invf = 1.0 / pow(10000.0, (double)(2 * i) / 128.0);
        float invff = (float)invf;
        int t0 = (blk - 8192) * 32;
        for (int j = 0; j < 32; j++) {
            int t = t0 + j;
            float angle = (float)t * invff;
            float s, c;
            sincosf(angle, &s, &c);
            g_cos[t * 64 + i] = __bfloat162float(__float2bfloat16(c));
            g_sin[t * 64 + i] = __bfloat162float(__float2bfloat16(s));
        }
        if (blk == 8192 && i == 0) {
            float s1 = 0.f, s2 = 0.f;
            for (int j = 0; j < 64; j++) { s1 += lq1[j] * lk1[j]; s2 += lq2[j] * lk2[j]; }
            g_lam = expf(s1) - expf(s2) + 0.2f;
        }
        return;
    }
    int base = blk * 512 + threadIdx.x;
#pragma unroll
    for (int r = 0; r < 2; r++) {
        int j = base + r * 256;                  // flat float4 index, [0, 4194304)
        const float* s;
        bf16 *dh, *dl;
        if (j < 2097152) {                       // x
            s  = x + (size_t)j * 4;
            dh = g_xh + (size_t)j * 4;
            dl = g_xl + (size_t)j * 4;
        } else {                                 // W region: dst f4 index = jw for all three
            int jw = j - 2097152;
            if (jw < 1048576)       s = wq + (size_t)jw * 4;
            else if (jw < 1572864)  s = wk + (size_t)(jw - 1048576) * 4;
            else                    s = wv + (size_t)(jw - 1572864) * 4;
            dh = g_wh + (size_t)jw * 4;
            dl = g_wl + (size_t)jw * 4;
        }
        float4 v = *(const float4*)s;
        uint32_t h0, l0, h1, l1;
        packhl(v.x, v.y, h0, l0);
        packhl(v.z, v.w, h1, l1);
        *(uint2*)dh = make_uint2(h0, h1);
        *(uint2*)dl = make_uint2(l0, l1);
    }
}

// ---------------- bf16x3 HMMA QKV GEMM (cp.async, 3-stage, 2 CTA/SM) [R13] ----------------
#define GEMM_SMEM 98304

__global__ __launch_bounds__(256, 2)
void qkv_gemm_tc(const float* __restrict__ scaler) {
    extern __shared__ char sm[];
    uint32_t sb = smem_u32(sm);
    int tid = threadIdx.x;
    int wid = tid >> 5, lane = tid & 31;
    int wy = wid >> 1, wx = wid & 1;

    int bid = blockIdx.x;
    int type, bx, by;
    if (bid < 512)      { type = 0; bx = bid & 15; by = bid >> 4; }
    else if (bid < 768) { int u = bid - 512; type = 1; bx = u & 7; by = u >> 3; }
    else                { int u = bid - 768; type = 2; bx = u & 7; by = u >> 3; }
    int row0 = by * 128, col0 = bx * 128;
    int wrow0 = col0 + (type == 0 ? 0 : (type == 1 ? 2048 : 3072));
    const bf16* pb[4] = { g_xh + (size_t)row0 * 2048, g_xl + (size_t)row0 * 2048,
                          g_wh + (size_t)wrow0 * 2048, g_wl + (size_t)wrow0 * 2048 };

    auto g_issue = [&](int kc, int slot) {
        uint32_t st = sb + slot * 32768;
#pragma unroll
        for (int it = 0; it < 8; it++) {
            int i = tid + it * 256;
            int plane = i >> 9, r = (i >> 2) & 127, ch = i & 3;
            const bf16* src = pb[plane] + (size_t)r * 2048 + kc * 32 + ch * 8;
            CP16(st + plane * 8192 + tchunk(r, ch), src);
        }
        CP_COMMIT();
    };

    int a_row = (lane & 7) + ((lane >> 3) & 1) * 8;
    int a_ch  = lane >> 4;
    int b_row = (lane & 7) + (lane >> 4) * 8;
    int b_ch  = (lane >> 3) & 1;
    uint32_t aoff[2][2], boff[4][2];
#pragma unroll
    for (int mt = 0; mt < 2; mt++)
#pragma unroll
        for (int ks = 0; ks < 2; ks++)
            aoff[mt][ks] = tchunk(wy * 32 + mt * 16 + a_row, 2 * ks + a_ch);
#pragma unroll
    for (int nb = 0; nb < 4; nb++)
#pragma unroll
        for (int ks = 0; ks < 2; ks++)
            boff[nb][ks] = tchunk(wx * 64 + nb * 16 + b_row, 2 * ks + b_ch);

    float acc[2][8][4];
#pragma unroll
    for (int i = 0; i < 2; i++)
#pragma unroll
        for (int j = 0; j < 8; j++)
#pragma unroll
            for (int k = 0; k < 4; k++) acc[i][j][k] = 0.f;

    g_issue(0, 0); g_issue(1, 1);
    for (int kc = 0; kc < 64; kc++) {
        if (kc + 1 < 64) { CP_WAIT(1); }
        else             { CP_WAIT(0); }
        __syncthreads();
        if (kc + 2 < 64) g_issue(kc + 2, (kc + 2) % 3);
        uint32_t stb = sb + (kc % 3) * 32768;
#pragma unroll
        for (int ks = 0; ks < 2; ks++) {
            uint32_t Ahf[2][4], Alf[2][4];
#pragma unroll
            for (int mt = 0; mt < 2; mt++) {
                ldm4(Ahf[mt], stb + aoff[mt][ks]);
                ldm4(Alf[mt], stb + 8192 + aoff[mt][ks]);
            }
#pragma unroll
            for (int nb = 0; nb < 4; nb++) {
                uint32_t rh[4], rl[4];
                ldm4(rh, stb + 16384 + boff[nb][ks]);
                ldm4(rl, stb + 24576 + boff[nb][ks]);
                uint32_t bh0[2] = {rh[0], rh[1]}, bh1[2] = {rh[2], rh[3]};
                uint32_t bl0[2] = {rl[0], rl[1]}, bl1[2] = {rl[2], rl[3]};
#pragma unroll
                for (int mt = 0; mt < 2; mt++) {
                    MMA(acc[mt][2*nb],   Ahf[mt], bh0);
                    MMA(acc[mt][2*nb],   Ahf[mt], bl0);
                    MMA(acc[mt][2*nb],   Alf[mt], bh0);
                    MMA(acc[mt][2*nb+1], Ahf[mt], bh1);
                    MMA(acc[mt][2*nb+1], Ahf[mt], bl1);
                    MMA(acc[mt][2*nb+1], Alf[mt], bh1);
                }
            }
        }
    }
    __syncthreads();

    float* buf1 = (float*)sm;   // [128][132]
#pragma unroll
    for (int mt = 0; mt < 2; mt++)
#pragma unroll
        for (int n = 0; n < 8; n++) {
            int r = wy * 32 + mt * 16 + (lane >> 2);
            int c = wx * 64 + n * 8 + (lane & 3) * 2;
            *(float2*)&buf1[r * 132 + c]       = make_float2(acc[mt][n][0], acc[mt][n][1]);
            *(float2*)&buf1[(r + 8) * 132 + c] = make_float2(acc[mt][n][2], acc[mt][n][3]);
        }
    __syncthreads();

    if (type == 2) {
        for (int i = tid; i < 4096; i += 256) {
            int r = i >> 5, c4 = i & 31;
            float4 v = *(const float4*)&buf1[r * 132 + c4 * 4];
            uint32_t h0, l0, h1, l1;
            packhl(v.x, v.y, h0, l0); packhl(v.z, v.w, h1, l1);
            size_t off = (size_t)(row0 + r) * 1024 + col0 + c4 * 4;
            *(uint2*)(g_Vh + off) = make_uint2(h0, h1);
            *(uint2*)(g_Vl + off) = make_uint2(l0, l1);
        }
        return;
    }

    if (tid < 128) {
        int b = row0 >> 11;
        int t = (row0 & (T_ - 1)) + tid;
        const float* rowp = &buf1[tid * 132];
        float ss = 0.f;
#pragma unroll
        for (int c4 = 0; c4 < 32; c4++) {
            float4 v = *(const float4*)&rowp[c4 * 4];
            ss = fmaf(v.x, v.x, fmaf(v.y, v.y, fmaf(v.z, v.z, fmaf(v.w, v.w, ss))));
        }
        float rn = rsqrtf(ss * (1.0f / 128.0f) + 1.1920929e-07f);
        float f = (type == 0) ? rn * scaler[bx] * logf((float)(t + 1)) *
                                0.08838834764831845f * 1.4426950408889634f
                              : rn;
        float ov[128];
#pragma unroll
        for (int i = 0; i < 64; i++) {
            float c = g_cos[t * 64 + i], s = g_sin[t * 64 + i];
            float x1 = rowp[i], x2 = rowp[i + 64];
            ov[i]      = ( x1 * c + x2 * s) * f;
            ov[i + 64] = (-x1 * s + x2 * c) * f;
        }
        size_t rbase;
        bf16 *dh, *dl;
        if (type == 0) {
            rbase = ((size_t)((b * 2 + (bx >> 3)) * 8 + (bx & 7)) * T_ + t) * 128;
            dh = g_Qh + rbase; dl = g_Ql + rbase;
        } else {
            rbase = ((size_t)((b * 2 + (bx >> 2)) * 4 + (bx & 3)) * T_ + t) * 128;
            dh = g_Kh + rbase; dl = g_Kl + rbase;
        }
#pragma unroll
        for (int c4 = 0; c4 < 32; c4++) {
            uint32_t h0, l0, h1, l1;
            packhl(ov[c4*4], ov[c4*4+1], h0, l0);
            packhl(ov[c4*4+2], ov[c4*4+3], h1, l1);
            *(uint2*)(dh + c4 * 4) = make_uint2(h0, h1);
            *(uint2*)(dl + c4 * 4) = make_uint2(l0, l1);
        }
    }
}

// ---------------- HMMA diff causal flash attention (R13: S dedup + PV/softmax overlap) ----
#define STAT_MAX 196608
#define STAT_SUM 197120
#define P_BASE   197632
#define P_BUF    12288
#define ATT_SMEM (P_BASE + 2 * P_BUF)

__global__ __launch_bounds__(256, 1) void diff_attn_hmma(float* __restrict__ out) {
    extern __shared__ char sm[];
    uint32_t sb = smem_u32(sm);
    int tid = threadIdx.x, lane = tid & 31, wid = tid >> 5;
    int y = wid >> 2, qs = (wid >> 1) & 1, vh = wid & 1;
    int qt = 63 - blockIdx.x;
    int h = blockIdx.y, b = blockIdx.z;
    int q0 = qt * 32;
    int g = lane >> 2, t2 = (lane & 3) << 1;
    int kh = h >> 1;
    int widx  = (y * 2 + qs) * 2 + vh;
    int pwidx = widx ^ 1;

    const bf16* Kp[2][2];
    Kp[0][0] = g_Kh + ((size_t)((b * 2 + 0) * 4 + kh) * T_) * 128;
    Kp[0][1] = g_Kl + ((size_t)((b * 2 + 0) * 4 + kh) * T_) * 128;
    Kp[1][0] = g_Kh + ((size_t)((b * 2 + 1) * 4 + kh) * T_) * 128;
    Kp[1][1] = g_Kl + ((size_t)((b * 2 + 1) * 4 + kh) * T_) * 128;
    const bf16* Vp[2];
    Vp[0] = g_Vh + (size_t)b * T_ * 1024 + kh * 256;
    Vp[1] = g_Vl + (size_t)b * T_ * 1024 + kh * 256;

    uint32_t Qh[8][4], Ql[8][4];
    {
        const bf16* Qp[2][2];
        Qp[0][0] = g_Qh + ((size_t)((b * 2 + 0) * 8 + h) * T_ + q0) * 128;
        Qp[0][1] = g_Ql + ((size_t)((b * 2 + 0) * 8 + h) * T_ + q0) * 128;
        Qp[1][0] = g_Qh + ((size_t)((b * 2 + 1) * 8 + h) * T_ + q0) * 128;
        Qp[1][1] = g_Ql + ((size_t)((b * 2 + 1) * 8 + h) * T_ + q0) * 128;
#pragma unroll
        for (int it = 0; it < 8; it++) {
            int i = tid + it * 256;
            int br = i >> 10, hl = (i >> 9) & 1, qq = (i >> 4) & 31, c = i & 15;
            uint4 v = *(const uint4*)(Qp[br][hl] + (size_t)qq * 128 + c * 8);
            *(uint4*)(sm + ((br * 2 + hl) * 4 + (c >> 2)) * 2048 + tchunk(qq, c & 3)) = v;
        }
        __syncthreads();
        int a_row = (lane & 7) + ((lane >> 3) & 1) * 8;
        int a_ch  = lane >> 4;
#pragma unroll
        for (int kc = 0; kc < 8; kc++) {
            uint32_t off = tchunk(qs * 16 + a_row, 2 * (kc & 1) + a_ch);
            ldm4(Qh[kc], sb + ((y * 2 + 0) * 4 + (kc >> 1)) * 2048 + off);
            ldm4(Ql[kc], sb + ((y * 2 + 1) * 4 + (kc >> 1)) * 2048 + off);
        }
        __syncthreads();
    }

    float m0 = -INFINITY, m1 = -INFINITY, l0 = 0.f, l1 = 0.f;
    float oacc[16][4];
#pragma unroll
    for (int n = 0; n < 16; n++)
#pragma unroll
        for (int j = 0; j < 4; j++) oacc[n][j] = 0.f;

    int b_row = (lane & 7) + (lane >> 4) * 8;
    int b_ch  = (lane >> 3) & 1;
    uint32_t kboff[2];
#pragma unroll
    for (int ks = 0; ks < 2; ks++)
        kboff[ks] = tchunk(vh * 16 + b_row, 2 * ks + b_ch);

    float* SMAX = (float*)(sm + STAT_MAX);
    float* SSUM = (float*)(sm + STAT_SUM);
    uint32_t pw_lane_off = (uint32_t)((lane & 15) * 48 + (lane >> 4) * 16);

    int nt = qt + 1;

    auto stage_issue = [&](int kt, int slot) {
        uint32_t kb = sb + slot * 65536;
        uint32_t vb = kb + 32768;
        int k0 = kt * 32;
#pragma unroll
        for (int it = 0; it < 8; it++) {
            int i = tid + it * 256;
            int br = i >> 10, hl = (i >> 9) & 1, kk = (i >> 4) & 31, c = i & 15;
            const bf16* src = Kp[br][hl] + (size_t)(k0 + kk) * 128 + c * 8;
            CP16(kb + ((br * 2 + hl) * 4 + (c >> 2)) * 2048 + tchunk(kk, c & 3), src);
        }
#pragma unroll
        for (int it = 0; it < 8; it++) {
            int i = tid + it * 256;
            int hl = i >> 10, kk = (i >> 5) & 31, c = i & 31;
            const bf16* src = Vp[hl] + (size_t)(k0 + kk) * 1024 + c * 8;
            CP16(vb + hl * 16384 + kk * 512 + ((c ^ (kk & 7)) << 4), src);
        }
        CP_COMMIT();
    };

    uint32_t pha[4], pla[4];

    auto pv_accum = [&](uint32_t vbp, int pbuf) {
        uint32_t PR = sb + P_BASE + (uint32_t)pbuf * P_BUF + (uint32_t)pwidx * 1536 +
                      pw_lane_off;
        uint32_t phP[4], plP[4];
        ldm4(phP, PR);
        ldm4(plP, PR + 768);
#pragma unroll
        for (int kk = 0; kk < 2; kk++) {
            const uint32_t* PH = (kk == vh) ? pha : phP;
            const uint32_t* PL = (kk == vh) ? pla : plP;
            int krow = kk * 16 + (lane & 15);
            uint32_t rowadr = (uint32_t)(krow * 512);
            int swz = krow & 7;
#pragma unroll
            for (int ng = 0; ng < 8; ng++) {
                int lch = vh * 16 + ng * 2 + (lane >> 4);
                uint32_t ah = vbp + rowadr + (uint32_t)((lch ^ swz) << 4);
                uint32_t r4[4];
                ldm4t(r4, ah);
                uint32_t bvh0[2] = {r4[0], r4[1]}, bvh1[2] = {r4[2], r4[3]};
                uint32_t s4[4];
                ldm4t(s4, ah + 16384);
                uint32_t bvl0[2] = {s4[0], s4[1]}, bvl1[2] = {s4[2], s4[3]};
                MMA(oacc[2*ng],   PH, bvh0);
                MMA(oacc[2*ng],   PH, bvl0);
                MMA(oacc[2*ng],   PL, bvh0);
                MMA(oacc[2*ng+1], PH, bvh1);
                MMA(oacc[2*ng+1], PH, bvl1);
                MMA(oacc[2*ng+1], PL, bvh1);
            }
        }
    };

    stage_issue(0, 0);
    if (nt > 1) stage_issue(1, 1);
    for (int kt = 0; kt < nt; kt++) {
        if (kt + 1 < nt) { CP_WAIT(1); }
        else             { CP_WAIT(0); }
        __syncthreads();
        uint32_t kb = sb + (kt % 3) * 65536;
        int k0 = kt * 32;

        float sh[2][4], sca[2][4], scb[2][4];
#pragma unroll
        for (int n = 0; n < 2; n++)
#pragma unroll
            for (int j = 0; j < 4; j++) { sh[n][j] = 0.f; sca[n][j] = 0.f; scb[n][j] = 0.f; }
#pragma unroll
        for (int kc = 0; kc < 8; kc++) {
            uint32_t ph_ = kb + ((y * 2 + 0) * 4 + (kc >> 1)) * 2048;
            uint32_t pl_ = kb + ((y * 2 + 1) * 4 + (kc >> 1)) * 2048;
            uint32_t off = kboff[kc & 1];
            uint32_t rh[4], rl[4];
            ldm4(rh, ph_ + off);
            ldm4(rl, pl_ + off);
            uint32_t bh0[2] = {rh[0], rh[1]}, bh1[2] = {rh[2], rh[3]};
            uint32_t bl0[2] = {rl[0], rl[1]}, bl1[2] = {rl[2], rl[3]};
            MMA(sh[0],  Qh[kc], bh0);
            MMA(sca[0], Qh[kc], bl0);
            MMA(scb[0], Ql[kc], bh0);
            MMA(sh[1],  Qh[kc], bh1);
            MMA(sca[1], Qh[kc], bl1);
            MMA(scb[1], Ql[kc], bh1);
        }
#pragma unroll
        for (int n = 0; n < 2; n++)
#pragma unroll
            for (int j = 0; j < 4; j++) sh[n][j] += sca[n][j] + scb[n][j];

        if (kt == qt) {
            int r0 = q0 + qs * 16 + g, r1 = r0 + 8;
#pragma unroll
            for (int n = 0; n < 2; n++) {
                int c = k0 + vh * 16 + n * 8 + t2;
                if (c     > r0) sh[n][0] = -INFINITY;
                if (c + 1 > r0) sh[n][1] = -INFINITY;
                if (c     > r1) sh[n][2] = -INFINITY;
                if (c + 1 > r1) sh[n][3] = -INFINITY;
            }
        }

        if (kt > 0) pv_accum(sb + ((kt + 2) % 3) * 65536 + 32768, (kt - 1) & 1);

        float mx0 = fmaxf(fmaxf(sh[0][0], sh[0][1]), fmaxf(sh[1][0], sh[1][1]));
        float mx1 = fmaxf(fmaxf(sh[0][2], sh[0][3]), fmaxf(sh[1][2], sh[1][3]));
        mx0 = fmaxf(mx0, __shfl_xor_sync(0xffffffffu, mx0, 1));
        mx0 = fmaxf(mx0, __shfl_xor_sync(0xffffffffu, mx0, 2));
        mx1 = fmaxf(mx1, __shfl_xor_sync(0xffffffffu, mx1, 1));
        mx1 = fmaxf(mx1, __shfl_xor_sync(0xffffffffu, mx1, 2));
        if ((lane & 3) == 0) {
            SMAX[widx * 16 + g]     = mx0;
            SMAX[widx * 16 + g + 8] = mx1;
        }
        __syncthreads();
        float mn0 = fmaxf(m0, fmaxf(mx0, SMAX[pwidx * 16 + g]));
        float mn1 = fmaxf(m1, fmaxf(mx1, SMAX[pwidx * 16 + g + 8]));
        float a0 = ex2f(m0 - mn0), a1 = ex2f(m1 - mn1);
        m0 = mn0; m1 = mn1;

        float s0 = 0.f, s1 = 0.f;
#pragma unroll
        for (int n = 0; n < 2; n++) {
            sh[n][0] = ex2f(sh[n][0] - mn0); s0 += sh[n][0];
            sh[n][1] = ex2f(sh[n][1] - mn0); s0 += sh[n][1];
            sh[n][2] = ex2f(sh[n][2] - mn1); s1 += sh[n][2];
            sh[n][3] = ex2f(sh[n][3] - mn1); s1 += sh[n][3];
        }
        s0 += __shfl_xor_sync(0xffffffffu, s0, 1);
        s0 += __shfl_xor_sync(0xffffffffu, s0, 2);
        s1 += __shfl_xor_sync(0xffffffffu, s1, 1);
        s1 += __shfl_xor_sync(0xffffffffu, s1, 2);

        packhl(sh[0][0], sh[0][1], pha[0], pla[0]);
        packhl(sh[0][2], sh[0][3], pha[1], pla[1]);
        packhl(sh[1][0], sh[1][1], pha[2], pla[2]);
        packhl(sh[1][2], sh[1][3], pha[3], pla[3]);
        {
            char* PW = sm + P_BASE + (kt & 1) * P_BUF + widx * 1536;
            *(uint32_t*)(PW + g * 48 + t2 * 2)              = pha[0];
            *(uint32_t*)(PW + (g + 8) * 48 + t2 * 2)        = pha[1];
            *(uint32_t*)(PW + g * 48 + 16 + t2 * 2)         = pha[2];
            *(uint32_t*)(PW + (g + 8) * 48 + 16 + t2 * 2)   = pha[3];
            *(uint32_t*)(PW + 768 + g * 48 + t2 * 2)            = pla[0];
            *(uint32_t*)(PW + 768 + (g + 8) * 48 + t2 * 2)      = pla[1];
            *(uint32_t*)(PW + 768 + g * 48 + 16 + t2 * 2)       = pla[2];
            *(uint32_t*)(PW + 768 + (g + 8) * 48 + 16 + t2 * 2) = pla[3];
        }
        if ((lane & 3) == 0) {
            SSUM[widx * 16 + g]     = s0;
            SSUM[widx * 16 + g + 8] = s1;
        }
        __syncthreads();
        l0 = l0 * a0 + s0 + SSUM[pwidx * 16 + g];
        l1 = l1 * a1 + s1 + SSUM[pwidx * 16 + g + 8];

        if (!__all_sync(0xffffffffu, (a0 == 1.f) && (a1 == 1.f))) {
#pragma unroll
            for (int n = 0; n < 16; n++) {
                oacc[n][0] *= a0; oacc[n][1] *= a0;
                oacc[n][2] *= a1; oacc[n][3] *= a1;
            }
        }

        if (kt + 2 < nt) stage_issue(kt + 2, (kt + 2) % 3);
    }
    pv_accum(sb + ((nt - 1) % 3) * 65536 + 32768, (nt - 1) & 1);

    __syncthreads();
    float i0 = 1.f / l0, i1 = 1.f / l1;
    float* Ob = (float*)sm + y * 8192;
#pragma unroll
    for (int n = 0; n < 16; n++) {
        int col = vh * 128 + n * 8 + t2;
        int r = qs * 16 + g;
        Ob[r * 256 + col]           = oacc[n][0] * i0;
        Ob[r * 256 + col + 1]       = oacc[n][1] * i0;
        Ob[(r + 8) * 256 + col]     = oacc[n][2] * i1;
        Ob[(r + 8) * 256 + col + 1] = oacc[n][3] * i1;
    }
    __syncthreads();
    float lam = g_lam;
    float* O0 = (float*)sm;
    float* O1 = (float*)sm + 8192;
    for (int i = tid; i < 2048; i += 256) {
        int r = i >> 6, c4 = i & 63;
        float4 v1 = *(const float4*)&O0[r * 256 + c4 * 4];
        float4 v2 = *(const float4*)&O1[r * 256 + c4 * 4];
        float4 o = {v1.x - lam * v2.x, v1.y - lam * v2.y,
                    v1.z - lam * v2.z, v1.w - lam * v2.w};
        *(float4*)&out[((size_t)(b * T_ + q0 + r) * 8 + h) * 256 + c4 * 4] = o;
    }
}

// ---------------- launch ----------------
extern "C" void kernel_launch(void* const* d_in, const int* in_sizes, int n_in,
                              void* d_out, int out_size) {
    const float* x      = (const float*)d_in[0];
    const float* Wq     = (const float*)d_in[1];
    const float* Wk     = (const float*)d_in[2];
    const float* Wv     = (const float*)d_in[3];
    const float* lq1    = (const float*)d_in[4];
    const float* lk1    = (const float*)d_in[5];
    const float* lq2    = (const float*)d_in[6];
    const float* lk2    = (const float*)d_in[7];
    const float* scaler = (const float*)d_in[8];
    float* out = (float*)d_out;

    prep_kernel<<<8256, 256>>>(x, Wq, Wk, Wv, lq1, lk1, lq2, lk2);

    cudaFuncSetAttribute(qkv_gemm_tc, cudaFuncAttributeMaxDynamicSharedMemorySize, GEMM_SMEM);
    qkv_gemm_tc<<<1024, 256, GEMM_SMEM>>>(scaler);

    cudaFuncSetAttribute(diff_attn_hmma, cudaFuncAttributeMaxDynamicSharedMemorySize, ATT_SMEM);
    diff_attn_hmma<<<dim3(64, 8, B_), 256, ATT_SMEM>>>(out);
}

// round 17
// speedup vs baseline: 1.1197x; 1.0884x over previous
#include <cuda_runtime.h>
#include <cuda_bf16.h>
#include <cuda_fp16.h>
#include <math.h>
#include <stdint.h>

#define B_  2
#define T_  2048
typedef __nv_bfloat16 bf16;

// ---------------- scratch ----------------
__device__ bf16 g_xh[(size_t)4096 * 2048];             // x hi/lo
__device__ bf16 g_xl[(size_t)4096 * 2048];
__device__ bf16 g_wh[(size_t)4096 * 2048];             // [Wq | Wk | Wv] rows
__device__ bf16 g_wl[(size_t)4096 * 2048];
__device__ bf16 g_Qh[(size_t)B_ * 2 * 8 * T_ * 128];   // [b][y][h][t][d] hi (log2e-scaled)
__device__ bf16 g_Ql[(size_t)B_ * 2 * 8 * T_ * 128];
__device__ bf16 g_Kh[(size_t)B_ * 2 * 4 * T_ * 128];   // [b][y][kh][t][d]
__device__ bf16 g_Kl[(size_t)B_ * 2 * 4 * T_ * 128];
__device__ __half g_V16[(size_t)B_ * T_ * 1024];       // [b*t][vh*256+vd] fp16 single plane
__device__ float g_cos[T_ * 64];
__device__ float g_sin[T_ * 64];
__device__ float g_lam;

// ---------------- helpers ----------------
__device__ __forceinline__ uint32_t smem_u32(const void* p) {
    uint32_t a;
    asm("{ .reg .u64 t; cvta.to.shared.u64 t, %1; cvt.u32.u64 %0, t; }" : "=r"(a) : "l"(p));
    return a;
}
__device__ __forceinline__ void ldm4(uint32_t* r, uint32_t a) {
    asm volatile("ldmatrix.sync.aligned.m8n8.x4.shared.b16 {%0,%1,%2,%3}, [%4];"
                 : "=r"(r[0]), "=r"(r[1]), "=r"(r[2]), "=r"(r[3]) : "r"(a));
}
__device__ __forceinline__ void ldm4t(uint32_t* r, uint32_t a) {
    asm volatile("ldmatrix.sync.aligned.m8n8.x4.trans.shared.b16 {%0,%1,%2,%3}, [%4];"
                 : "=r"(r[0]), "=r"(r[1]), "=r"(r[2]), "=r"(r[3]) : "r"(a));
}
__device__ __forceinline__ float ex2f(float x) {
    float y;
    asm("ex2.approx.ftz.f32 %0, %1;" : "=f"(y) : "f"(x));
    return y;
}
#define MMA(d, a, b)                                                          \
    asm volatile("mma.sync.aligned.m16n8k16.row.col.f32.bf16.bf16.f32 "       \
                 "{%0,%1,%2,%3}, {%4,%5,%6,%7}, {%8,%9}, {%0,%1,%2,%3};"      \
                 : "+f"(d[0]), "+f"(d[1]), "+f"(d[2]), "+f"(d[3])             \
                 : "r"(a[0]), "r"(a[1]), "r"(a[2]), "r"(a[3]),                \
                   "r"(b[0]), "r"(b[1]))
#define MMA16(d, a, b)                                                        \
    asm volatile("mma.sync.aligned.m16n8k16.row.col.f32.f16.f16.f32 "         \
                 "{%0,%1,%2,%3}, {%4,%5,%6,%7}, {%8,%9}, {%0,%1,%2,%3};"      \
                 : "+f"(d[0]), "+f"(d[1]), "+f"(d[2]), "+f"(d[3])             \
                 : "r"(a[0]), "r"(a[1]), "r"(a[2]), "r"(a[3]),                \
                   "r"(b[0]), "r"(b[1]))
#define CP16(dst, src)                                                        \
    asm volatile("cp.async.cg.shared.global [%0], [%1], 16;" :: "r"(dst), "l"(src))
#define CP_COMMIT() asm volatile("cp.async.commit_group;" ::: "memory")
#define CP_WAIT(n)  asm volatile("cp.async.wait_group %0;" :: "n"(n) : "memory")

__device__ __forceinline__ uint32_t tchunk(int r, int c) {
    return (uint32_t)(((r >> 1) << 7) + ((((((r & 1) << 2) | c)) ^ ((r >> 1) & 7)) << 4));
}
__device__ __forceinline__ uint32_t pk2(float x, float y) {
    __nv_bfloat162 h;
    h.x = __float2bfloat16(x);
    h.y = __float2bfloat16(y);
    return *reinterpret_cast<uint32_t*>(&h);
}
__device__ __forceinline__ uint32_t pk2h(float x, float y) {
    __half2 h;
    h.x = __float2half(x);
    h.y = __float2half(y);
    return *reinterpret_cast<uint32_t*>(&h);
}
__device__ __forceinline__ void packhl(float x, float y, uint32_t& hi, uint32_t& lo) {
    bf16 hx = __float2bfloat16(x), hy = __float2bfloat16(y);
    __nv_bfloat162 h; h.x = hx; h.y = hy;
    hi = *reinterpret_cast<uint32_t*>(&h);
    lo = pk2(x - __bfloat162float(hx), y - __bfloat162float(hy));
}
__device__ __forceinline__ void packhl16(float x, float y, uint32_t& hi, uint32_t& lo) {
    __half hx = __float2half(x), hy = __float2half(y);
    __half2 h; h.x = hx; h.y = hy;
    hi = *reinterpret_cast<uint32_t*>(&h);
    lo = pk2h(x - __half2float(hx), y - __half2float(hy));
}

// ---------------- prep: hi/lo split (flat, 2 f4/thread) + RoPE + lambda ----------------
__global__ __launch_bounds__(256) void prep_kernel(const float* __restrict__ x,
                                                   const float* __restrict__ wq,
                                                   const float* __restrict__ wk,
                                                   const float* __restrict__ wv,
                                                   const float* __restrict__ lq1,
                                                   const float* __restrict__ lk1,
                                                   const float* __restrict__ lq2,
                                                   const float* __restrict__ lk2) {
    int blk = blockIdx.x;
    if (blk >= 8192) {
        if (threadIdx.x >= 64) return;
        int i = threadIdx.x;
        double invf = 1.0 / pow(10000.0, (double)(2 * i) / 128.0);
        float invff = (float)invf;
        int t0 = (blk - 8192) * 32;
        for (int j = 0; j < 32; j++) {
            int t = t0 + j;
            float angle = (float)t * invff;
            float s, c;
            sincosf(angle, &s, &c);
            g_cos[t * 64 + i] = __bfloat162float(__float2bfloat16(c));
            g_sin[t * 64 + i] = __bfloat162float(__float2bfloat16(s));
        }
        if (blk == 8192 && i == 0) {
            float s1 = 0.f, s2 = 0.f;
            for (int j = 0; j < 64; j++) { s1 += lq1[j] * lk1[j]; s2 += lq2[j] * lk2[j]; }
            g_lam = expf(s1) - expf(s2) + 0.2f;
        }
        return;
    }
    int base = blk * 512 + threadIdx.x;
#pragma unroll
    for (int r = 0; r < 2; r++) {
        int j = base + r * 256;
        const float* s;
        bf16 *dh, *dl;
        if (j < 2097152) {
            s  = x + (size_t)j * 4;
            dh = g_xh + (size_t)j * 4;
            dl = g_xl + (size_t)j * 4;
        } else {
            int jw = j - 2097152;
            if (jw < 1048576)       s = wq + (size_t)jw * 4;
            else if (jw < 1572864)  s = wk + (size_t)(jw - 1048576) * 4;
            else                    s = wv + (size_t)(jw - 1572864) * 4;
            dh = g_wh + (size_t)jw * 4;
            dl = g_wl + (size_t)jw * 4;
        }
        float4 v = *(const float4*)s;
        uint32_t h0, l0, h1, l1;
        packhl(v.x, v.y, h0, l0);
        packhl(v.z, v.w, h1, l1);
        *(uint2*)dh = make_uint2(h0, h1);
        *(uint2*)dl = make_uint2(l0, l1);
    }
}

// ---------------- bf16x3 HMMA QKV GEMM (cp.async, 3-stage, 2 CTA/SM) [R13] ----------------
#define GEMM_SMEM 98304

__global__ __launch_bounds__(256, 2)
void qkv_gemm_tc(const float* __restrict__ scaler) {
    extern __shared__ char sm[];
    uint32_t sb = smem_u32(sm);
    int tid = threadIdx.x;
    int wid = tid >> 5, lane = tid & 31;
    int wy = wid >> 1, wx = wid & 1;

    int bid = blockIdx.x;
    int type, bx, by;
    if (bid < 512)      { type = 0; bx = bid & 15; by = bid >> 4; }
    else if (bid < 768) { int u = bid - 512; type = 1; bx = u & 7; by = u >> 3; }
    else                { int u = bid - 768; type = 2; bx = u & 7; by = u >> 3; }
    int row0 = by * 128, col0 = bx * 128;
    int wrow0 = col0 + (type == 0 ? 0 : (type == 1 ? 2048 : 3072));
    const bf16* pb[4] = { g_xh + (size_t)row0 * 2048, g_xl + (size_t)row0 * 2048,
                          g_wh + (size_t)wrow0 * 2048, g_wl + (size_t)wrow0 * 2048 };

    auto g_issue = [&](int kc, int slot) {
        uint32_t st = sb + slot * 32768;
#pragma unroll
        for (int it = 0; it < 8; it++) {
            int i = tid + it * 256;
            int plane = i >> 9, r = (i >> 2) & 127, ch = i & 3;
            const bf16* src = pb[plane] + (size_t)r * 2048 + kc * 32 + ch * 8;
            CP16(st + plane * 8192 + tchunk(r, ch), src);
        }
        CP_COMMIT();
    };

    int a_row = (lane & 7) + ((lane >> 3) & 1) * 8;
    int a_ch  = lane >> 4;
    int b_row = (lane & 7) + (lane >> 4) * 8;
    int b_ch  = (lane >> 3) & 1;
    uint32_t aoff[2][2], boff[4][2];
#pragma unroll
    for (int mt = 0; mt < 2; mt++)
#pragma unroll
        for (int ks = 0; ks < 2; ks++)
            aoff[mt][ks] = tchunk(wy * 32 + mt * 16 + a_row, 2 * ks + a_ch);
#pragma unroll
    for (int nb = 0; nb < 4; nb++)
#pragma unroll
        for (int ks = 0; ks < 2; ks++)
            boff[nb][ks] = tchunk(wx * 64 + nb * 16 + b_row, 2 * ks + b_ch);

    float acc[2][8][4];
#pragma unroll
    for (int i = 0; i < 2; i++)
#pragma unroll
        for (int j = 0; j < 8; j++)
#pragma unroll
            for (int k = 0; k < 4; k++) acc[i][j][k] = 0.f;

    g_issue(0, 0); g_issue(1, 1);
    for (int kc = 0; kc < 64; kc++) {
        if (kc + 1 < 64) { CP_WAIT(1); }
        else             { CP_WAIT(0); }
        __syncthreads();
        if (kc + 2 < 64) g_issue(kc + 2, (kc + 2) % 3);
        uint32_t stb = sb + (kc % 3) * 32768;
#pragma unroll
        for (int ks = 0; ks < 2; ks++) {
            uint32_t Ahf[2][4], Alf[2][4];
#pragma unroll
            for (int mt = 0; mt < 2; mt++) {
                ldm4(Ahf[mt], stb + aoff[mt][ks]);
                ldm4(Alf[mt], stb + 8192 + aoff[mt][ks]);
            }
#pragma unroll
            for (int nb = 0; nb < 4; nb++) {
                uint32_t rh[4], rl[4];
                ldm4(rh, stb + 16384 + boff[nb][ks]);
                ldm4(rl, stb + 24576 + boff[nb][ks]);
                uint32_t bh0[2] = {rh[0], rh[1]}, bh1[2] = {rh[2], rh[3]};
                uint32_t bl0[2] = {rl[0], rl[1]}, bl1[2] = {rl[2], rl[3]};
#pragma unroll
                for (int mt = 0; mt < 2; mt++) {
                    MMA(acc[mt][2*nb],   Ahf[mt], bh0);
                    MMA(acc[mt][2*nb],   Ahf[mt], bl0);
                    MMA(acc[mt][2*nb],   Alf[mt], bh0);
                    MMA(acc[mt][2*nb+1], Ahf[mt], bh1);
                    MMA(acc[mt][2*nb+1], Ahf[mt], bl1);
                    MMA(acc[mt][2*nb+1], Alf[mt], bh1);
                }
            }
        }
    }
    __syncthreads();

    float* buf1 = (float*)sm;   // [128][132]
#pragma unroll
    for (int mt = 0; mt < 2; mt++)
#pragma unroll
        for (int n = 0; n < 8; n++) {
            int r = wy * 32 + mt * 16 + (lane >> 2);
            int c = wx * 64 + n * 8 + (lane & 3) * 2;
            *(float2*)&buf1[r * 132 + c]       = make_float2(acc[mt][n][0], acc[mt][n][1]);
            *(float2*)&buf1[(r + 8) * 132 + c] = make_float2(acc[mt][n][2], acc[mt][n][3]);
        }
    __syncthreads();

    if (type == 2) {
        for (int i = tid; i < 4096; i += 256) {
            int r = i >> 5, c4 = i & 31;
            float4 v = *(const float4*)&buf1[r * 132 + c4 * 4];
            uint32_t h0 = pk2h(v.x, v.y), h1 = pk2h(v.z, v.w);
            *(uint2*)(g_V16 + (size_t)(row0 + r) * 1024 + col0 + c4 * 4) = make_uint2(h0, h1);
        }
        return;
    }

    if (tid < 128) {
        int b = row0 >> 11;
        int t = (row0 & (T_ - 1)) + tid;
        const float* rowp = &buf1[tid * 132];
        float ss = 0.f;
#pragma unroll
        for (int c4 = 0; c4 < 32; c4++) {
            float4 v = *(const float4*)&rowp[c4 * 4];
            ss = fmaf(v.x, v.x, fmaf(v.y, v.y, fmaf(v.z, v.z, fmaf(v.w, v.w, ss))));
        }
        float rn = rsqrtf(ss * (1.0f / 128.0f) + 1.1920929e-07f);
        float f = (type == 0) ? rn * scaler[bx] * logf((float)(t + 1)) *
                                0.08838834764831845f * 1.4426950408889634f
                              : rn;
        float ov[128];
#pragma unroll
        for (int i = 0; i < 64; i++) {
            float c = g_cos[t * 64 + i], s = g_sin[t * 64 + i];
            float x1 = rowp[i], x2 = rowp[i + 64];
            ov[i]      = ( x1 * c + x2 * s) * f;
            ov[i + 64] = (-x1 * s + x2 * c) * f;
        }
        size_t rbase;
        bf16 *dh, *dl;
        if (type == 0) {
            rbase = ((size_t)((b * 2 + (bx >> 3)) * 8 + (bx & 7)) * T_ + t) * 128;
            dh = g_Qh + rbase; dl = g_Ql + rbase;
        } else {
            rbase = ((size_t)((b * 2 + (bx >> 2)) * 4 + (bx & 3)) * T_ + t) * 128;
            dh = g_Kh + rbase; dl = g_Kl + rbase;
        }
#pragma unroll
        for (int c4 = 0; c4 < 32; c4++) {
            uint32_t h0, l0, h1, l1;
            packhl(ov[c4*4], ov[c4*4+1], h0, l0);
            packhl(ov[c4*4+2], ov[c4*4+3], h1, l1);
            *(uint2*)(dh + c4 * 4) = make_uint2(h0, h1);
            *(uint2*)(dl + c4 * 4) = make_uint2(l0, l1);
        }
    }
}

// ---------------- HMMA diff causal flash attention (fp16 V, P fp16 hi/lo) -----------------
// stage (48KB at slot*49152): K planes 32KB | V16 16KB
#define STG_SZ   49152
#define STAT_MAX (3 * STG_SZ)
#define STAT_SUM (STAT_MAX + 512)
#define P_BASE   (STAT_SUM + 512)
#define P_BUF    12288
#define ATT_SMEM (P_BASE + 2 * P_BUF)

__global__ __launch_bounds__(256, 1) void diff_attn_hmma(float* __restrict__ out) {
    extern __shared__ char sm[];
    uint32_t sb = smem_u32(sm);
    int tid = threadIdx.x, lane = tid & 31, wid = tid >> 5;
    int y = wid >> 2, qs = (wid >> 1) & 1, vh = wid & 1;
    int qt = 63 - blockIdx.x;
    int h = blockIdx.y, b = blockIdx.z;
    int q0 = qt * 32;
    int g = lane >> 2, t2 = (lane & 3) << 1;
    int kh = h >> 1;
    int widx  = (y * 2 + qs) * 2 + vh;
    int pwidx = widx ^ 1;

    const bf16* Kp[2][2];
    Kp[0][0] = g_Kh + ((size_t)((b * 2 + 0) * 4 + kh) * T_) * 128;
    Kp[0][1] = g_Kl + ((size_t)((b * 2 + 0) * 4 + kh) * T_) * 128;
    Kp[1][0] = g_Kh + ((size_t)((b * 2 + 1) * 4 + kh) * T_) * 128;
    Kp[1][1] = g_Kl + ((size_t)((b * 2 + 1) * 4 + kh) * T_) * 128;
    const __half* Vp0 = g_V16 + (size_t)b * T_ * 1024 + kh * 256;

    uint32_t Qh[8][4], Ql[8][4];
    {
        const bf16* Qp[2][2];
        Qp[0][0] = g_Qh + ((size_t)((b * 2 + 0) * 8 + h) * T_ + q0) * 128;
        Qp[0][1] = g_Ql + ((size_t)((b * 2 + 0) * 8 + h) * T_ + q0) * 128;
        Qp[1][0] = g_Qh + ((size_t)((b * 2 + 1) * 8 + h) * T_ + q0) * 128;
        Qp[1][1] = g_Ql + ((size_t)((b * 2 + 1) * 8 + h) * T_ + q0) * 128;
#pragma unroll
        for (int it = 0; it < 8; it++) {
            int i = tid + it * 256;
            int br = i >> 10, hl = (i >> 9) & 1, qq = (i >> 4) & 31, c = i & 15;
            uint4 v = *(const uint4*)(Qp[br][hl] + (size_t)qq * 128 + c * 8);
            *(uint4*)(sm + ((br * 2 + hl) * 4 + (c >> 2)) * 2048 + tchunk(qq, c & 3)) = v;
        }
        __syncthreads();
        int a_row = (lane & 7) + ((lane >> 3) & 1) * 8;
        int a_ch  = lane >> 4;
#pragma unroll
        for (int kc = 0; kc < 8; kc++) {
            uint32_t off = tchunk(qs * 16 + a_row, 2 * (kc & 1) + a_ch);
            ldm4(Qh[kc], sb + ((y * 2 + 0) * 4 + (kc >> 1)) * 2048 + off);
            ldm4(Ql[kc], sb + ((y * 2 + 1) * 4 + (kc >> 1)) * 2048 + off);
        }
        __syncthreads();
    }

    float m0 = -INFINITY, m1 = -INFINITY, l0 = 0.f, l1 = 0.f;
    float oacc[16][4];
#pragma unroll
    for (int n = 0; n < 16; n++)
#pragma unroll
        for (int j = 0; j < 4; j++) oacc[n][j] = 0.f;

    int b_row = (lane & 7) + (lane >> 4) * 8;
    int b_ch  = (lane >> 3) & 1;
    uint32_t kboff[2];
#pragma unroll
    for (int ks = 0; ks < 2; ks++)
        kboff[ks] = tchunk(vh * 16 + b_row, 2 * ks + b_ch);

    float* SMAX = (float*)(sm + STAT_MAX);
    float* SSUM = (float*)(sm + STAT_SUM);
    uint32_t pw_lane_off = (uint32_t)((lane & 15) * 48 + (lane >> 4) * 16);

    int nt = qt + 1;

    auto stage_issue = [&](int kt, int slot) {
        uint32_t kb = sb + slot * STG_SZ;
        uint32_t vb = kb + 32768;
        int k0 = kt * 32;
#pragma unroll
        for (int it = 0; it < 8; it++) {
            int i = tid + it * 256;
            int br = i >> 10, hl = (i >> 9) & 1, kk = (i >> 4) & 31, c = i & 15;
            const bf16* src = Kp[br][hl] + (size_t)(k0 + kk) * 128 + c * 8;
            CP16(kb + ((br * 2 + hl) * 4 + (c >> 2)) * 2048 + tchunk(kk, c & 3), src);
        }
#pragma unroll
        for (int it = 0; it < 4; it++) {
            int i = tid + it * 256;
            int kk = (i >> 5) & 31, c = i & 31;
            const __half* src = Vp0 + (size_t)(k0 + kk) * 1024 + c * 8;
            CP16(vb + kk * 512 + ((c ^ (kk & 7)) << 4), src);
        }
        CP_COMMIT();
    };

    uint32_t pha[4], pla[4];

    auto pv_accum = [&](uint32_t vbp, int pbuf) {
        uint32_t PR = sb + P_BASE + (uint32_t)pbuf * P_BUF + (uint32_t)pwidx * 1536 +
                      pw_lane_off;
        uint32_t phP[4], plP[4];
        ldm4(phP, PR);
        ldm4(plP, PR + 768);
#pragma unroll
        for (int kk = 0; kk < 2; kk++) {
            const uint32_t* PH = (kk == vh) ? pha : phP;
            const uint32_t* PL = (kk == vh) ? pla : plP;
            int krow = kk * 16 + (lane & 15);
            uint32_t rowadr = (uint32_t)(krow * 512);
            int swz = krow & 7;
#pragma unroll
            for (int ng = 0; ng < 8; ng++) {
                int lch = vh * 16 + ng * 2 + (lane >> 4);
                uint32_t ah = vbp + rowadr + (uint32_t)((lch ^ swz) << 4);
                uint32_t r4[4];
                ldm4t(r4, ah);
                uint32_t bvh0[2] = {r4[0], r4[1]}, bvh1[2] = {r4[2], r4[3]};
                MMA16(oacc[2*ng],   PH, bvh0);
                MMA16(oacc[2*ng],   PL, bvh0);
                MMA16(oacc[2*ng+1], PH, bvh1);
                MMA16(oacc[2*ng+1], PL, bvh1);
            }
        }
    };

    stage_issue(0, 0);
    if (nt > 1) stage_issue(1, 1);
    for (int kt = 0; kt < nt; kt++) {
        if (kt + 1 < nt) { CP_WAIT(1); }
        else             { CP_WAIT(0); }
        __syncthreads();
        uint32_t kb = sb + (kt % 3) * STG_SZ;
        int k0 = kt * 32;

        float sh[2][4], sca[2][4], scb[2][4];
#pragma unroll
        for (int n = 0; n < 2; n++)
#pragma unroll
            for (int j = 0; j < 4; j++) { sh[n][j] = 0.f; sca[n][j] = 0.f; scb[n][j] = 0.f; }
#pragma unroll
        for (int kc = 0; kc < 8; kc++) {
            uint32_t ph_ = kb + ((y * 2 + 0) * 4 + (kc >> 1)) * 2048;
            uint32_t pl_ = kb + ((y * 2 + 1) * 4 + (kc >> 1)) * 2048;
            uint32_t off = kboff[kc & 1];
            uint32_t rh[4], rl[4];
            ldm4(rh, ph_ + off);
            ldm4(rl, pl_ + off);
            uint32_t bh0[2] = {rh[0], rh[1]}, bh1[2] = {rh[2], rh[3]};
            uint32_t bl0[2] = {rl[0], rl[1]}, bl1[2] = {rl[2], rl[3]};
            MMA(sh[0],  Qh[kc], bh0);
            MMA(sca[0], Qh[kc], bl0);
            MMA(scb[0], Ql[kc], bh0);
            MMA(sh[1],  Qh[kc], bh1);
            MMA(sca[1], Qh[kc], bl1);
            MMA(scb[1], Ql[kc], bh1);
        }
#pragma unroll
        for (int n = 0; n < 2; n++)
#pragma unroll
            for (int j = 0; j < 4; j++) sh[n][j] += sca[n][j] + scb[n][j];

        if (kt == qt) {
            int r0 = q0 + qs * 16 + g, r1 = r0 + 8;
#pragma unroll
            for (int n = 0; n < 2; n++) {
                int c = k0 + vh * 16 + n * 8 + t2;
                if (c     > r0) sh[n][0] = -INFINITY;
                if (c + 1 > r0) sh[n][1] = -INFINITY;
                if (c     > r1) sh[n][2] = -INFINITY;
                if (c + 1 > r1) sh[n][3] = -INFINITY;
            }
        }

        if (kt > 0) pv_accum(sb + ((kt + 2) % 3) * STG_SZ + 32768, (kt - 1) & 1);

        float mx0 = fmaxf(fmaxf(sh[0][0], sh[0][1]), fmaxf(sh[1][0], sh[1][1]));
        float mx1 = fmaxf(fmaxf(sh[0][2], sh[0][3]), fmaxf(sh[1][2], sh[1][3]));
        mx0 = fmaxf(mx0, __shfl_xor_sync(0xffffffffu, mx0, 1));
        mx0 = fmaxf(mx0, __shfl_xor_sync(0xffffffffu, mx0, 2));
        mx1 = fmaxf(mx1, __shfl_xor_sync(0xffffffffu, mx1, 1));
        mx1 = fmaxf(mx1, __shfl_xor_sync(0xffffffffu, mx1, 2));
        if ((lane & 3) == 0) {
            SMAX[widx * 16 + g]     = mx0;
            SMAX[widx * 16 + g + 8] = mx1;
        }
        __syncthreads();
        float mn0 = fmaxf(m0, fmaxf(mx0, SMAX[pwidx * 16 + g]));
        float mn1 = fmaxf(m1, fmaxf(mx1, SMAX[pwidx * 16 + g + 8]));
        float a0 = ex2f(m0 - mn0), a1 = ex2f(m1 - mn1);
        m0 = mn0; m1 = mn1;

        float s0 = 0.f, s1 = 0.f;
#pragma unroll
        for (int n = 0; n < 2; n++) {
            sh[n][0] = ex2f(sh[n][0] - mn0); s0 += sh[n][0];
            sh[n][1] = ex2f(sh[n][1] - mn0); s0 += sh[n][1];
            sh[n][2] = ex2f(sh[n][2] - mn1); s1 += sh[n][2];
            sh[n][3] = ex2f(sh[n][3] - mn1); s1 += sh[n][3];
        }
        s0 += __shfl_xor_sync(0xffffffffu, s0, 1);
        s0 += __shfl_xor_sync(0xffffffffu, s0, 2);
        s1 += __shfl_xor_sync(0xffffffffu, s1, 1);
        s1 += __shfl_xor_sync(0xffffffffu, s1, 2);

        packhl16(sh[0][0], sh[0][1], pha[0], pla[0]);
        packhl16(sh[0][2], sh[0][3], pha[1], pla[1]);
        packhl16(sh[1][0], sh[1][1], pha[2], pla[2]);
        packhl16(sh[1][2], sh[1][3], pha[3], pla[3]);
        {
            char* PW = sm + P_BASE + (kt & 1) * P_BUF + widx * 1536;
            *(uint32_t*)(PW + g * 48 + t2 * 2)              = pha[0];
            *(uint32_t*)(PW + (g + 8) * 48 + t2 * 2)        = pha[1];
            *(uint32_t*)(PW + g * 48 + 16 + t2 * 2)         = pha[2];
            *(uint32_t*)(PW + (g + 8) * 48 + 16 + t2 * 2)   = pha[3];
            *(uint32_t*)(PW + 768 + g * 48 + t2 * 2)            = pla[0];
            *(uint32_t*)(PW + 768 + (g + 8) * 48 + t2 * 2)      = pla[1];
            *(uint32_t*)(PW + 768 + g * 48 + 16 + t2 * 2)       = pla[2];
            *(uint32_t*)(PW + 768 + (g + 8) * 48 + 16 + t2 * 2) = pla[3];
        }
        if ((lane & 3) == 0) {
            SSUM[widx * 16 + g]     = s0;
            SSUM[widx * 16 + g + 8] = s1;
        }
        __syncthreads();
        l0 = l0 * a0 + s0 + SSUM[pwidx * 16 + g];
        l1 = l1 * a1 + s1 + SSUM[pwidx * 16 + g + 8];

        if (!__all_sync(0xffffffffu, (a0 == 1.f) && (a1 == 1.f))) {
#pragma unroll
            for (int n = 0; n < 16; n++) {
                oacc[n][0] *= a0; oacc[n][1] *= a0;
                oacc[n][2] *= a1; oacc[n][3] *= a1;
            }
        }

        if (kt + 2 < nt) stage_issue(kt + 2, (kt + 2) % 3);
    }
    pv_accum(sb + ((nt - 1) % 3) * STG_SZ + 32768, (nt - 1) & 1);

    __syncthreads();
    float i0 = 1.f / l0, i1 = 1.f / l1;
    float* Ob = (float*)sm + y * 8192;
#pragma unroll
    for (int n = 0; n < 16; n++) {
        int col = vh * 128 + n * 8 + t2;
        int r = qs * 16 + g;
        Ob[r * 256 + col]           = oacc[n][0] * i0;
        Ob[r * 256 + col + 1]       = oacc[n][1] * i0;
        Ob[(r + 8) * 256 + col]     = oacc[n][2] * i1;
        Ob[(r + 8) * 256 + col + 1] = oacc[n][3] * i1;
    }
    __syncthreads();
    float lam = g_lam;
    float* O0 = (float*)sm;
    float* O1 = (float*)sm + 8192;
    for (int i = tid; i < 2048; i += 256) {
        int r = i >> 6, c4 = i & 63;
        float4 v1 = *(const float4*)&O0[r * 256 + c4 * 4];
        float4 v2 = *(const float4*)&O1[r * 256 + c4 * 4];
        float4 o = {v1.x - lam * v2.x, v1.y - lam * v2.y,
                    v1.z - lam * v2.z, v1.w - lam * v2.w};
        *(float4*)&out[((size_t)(b * T_ + q0 + r) * 8 + h) * 256 + c4 * 4] = o;
    }
}

// ---------------- launch ----------------
extern "C" void kernel_launch(void* const* d_in, const int* in_sizes, int n_in,
                              void* d_out, int out_size) {
    const float* x      = (const float*)d_in[0];
    const float* Wq     = (const float*)d_in[1];
    const float* Wk     = (const float*)d_in[2];
    const float* Wv     = (const float*)d_in[3];
    const float* lq1    = (const float*)d_in[4];
    const float* lk1    = (const float*)d_in[5];
    const float* lq2    = (const float*)d_in[6];
    const float* lk2    = (const float*)d_in[7];
    const float* scaler = (const float*)d_in[8];
    float* out = (float*)d_out;

    prep_kernel<<<8256, 256>>>(x, Wq, Wk, Wv, lq1, lk1, lq2, lk2);

    cudaFuncSetAttribute(qkv_gemm_tc, cudaFuncAttributeMaxDynamicSharedMemorySize, GEMM_SMEM);
    qkv_gemm_tc<<<1024, 256, GEMM_SMEM>>>(scaler);

    cudaFuncSetAttribute(diff_attn_hmma, cudaFuncAttributeMaxDynamicSharedMemorySize, ATT_SMEM);
    diff_attn_hmma<<<dim3(64, 8, B_), 256, ATT_SMEM>>>(out);
}